// round 6
// baseline (speedup 1.0000x reference)
#include <cuda_runtime.h>
#include <cuda_bf16.h>

#define N_NODES 100000

// Scratch: __device__ globals (zero-init at load). Replay invariant: at entry
// of every call, deg=0 (k_prep cleaned it last call); p/wacc/S are cleaned by
// k_deg itself before k_edge/k_node consume them.
__device__ float  g_deg [N_NODES];
__device__ float  g_dinv[N_NODES];
__device__ float4 g_y   [N_NODES];   // x * dinv (pre-scaled source features)
__device__ float  g_wacc[N_NODES];   // per-src sum of dinv[dst]
__device__ float4 g_p   [N_NODES];   // sum of y[src] per dst (dinv[dst] deferred)
__device__ float  g_S   [64];        // sum_s w[s] * relu(p_s @ W1 + b1)

// K1: in-degree count (dst half only), 4 edges/thread. Also zeroes p/wacc/S.
__global__ void k_deg(const int4* __restrict__ dst4, int E4) {
    int t = blockIdx.x * blockDim.x + threadIdx.x;
    if (t < N_NODES) {
        g_p[t]    = make_float4(0.f, 0.f, 0.f, 0.f);
        g_wacc[t] = 0.0f;
    }
    if (t < 64) g_S[t] = 0.0f;
    if (t >= E4) return;
    int4 d = dst4[t];
    if ((unsigned)d.x < (unsigned)N_NODES) atomicAdd(&g_deg[d.x], 1.0f);
    if ((unsigned)d.y < (unsigned)N_NODES) atomicAdd(&g_deg[d.y], 1.0f);
    if ((unsigned)d.z < (unsigned)N_NODES) atomicAdd(&g_deg[d.z], 1.0f);
    if ((unsigned)d.w < (unsigned)N_NODES) atomicAdd(&g_deg[d.w], 1.0f);
}

// K2: dinv = rsqrt(deg+1) (self loop), y = x*dinv. Resets deg for next replay.
__global__ void k_prep(const float4* __restrict__ x) {
    int i = blockIdx.x * blockDim.x + threadIdx.x;
    if (i >= N_NODES) return;
    float di = rsqrtf(g_deg[i] + 1.0f);
    g_deg[i]  = 0.0f;                 // self-clean (free: line already owned)
    g_dinv[i] = di;
    float4 xv = x[i];
    g_y[i] = make_float4(xv.x * di, xv.y * di, xv.z * di, xv.w * di);
}

// K3: fused edge pass, 4 edges/thread. Per edge (4 random L2 ops):
//   p[dst]   += y[src]        (RED.v4, payload straight from the gather)
//   wacc[src] += dinv[dst]    (RED scalar)
// All gathers issued before any RED for maximum MLP.
__global__ void k_edge(const int4* __restrict__ src4,
                       const int4* __restrict__ dst4,
                       int E4) {
    int t = blockIdx.x * blockDim.x + threadIdx.x;
    if (t >= E4) return;
    int4 s = src4[t];
    int4 d = dst4[t];
    bool ok0 = (unsigned)s.x < (unsigned)N_NODES && (unsigned)d.x < (unsigned)N_NODES;
    bool ok1 = (unsigned)s.y < (unsigned)N_NODES && (unsigned)d.y < (unsigned)N_NODES;
    bool ok2 = (unsigned)s.z < (unsigned)N_NODES && (unsigned)d.z < (unsigned)N_NODES;
    bool ok3 = (unsigned)s.w < (unsigned)N_NODES && (unsigned)d.w < (unsigned)N_NODES;
    float4 y0, y1, y2, y3;
    float nd0 = 0.f, nd1 = 0.f, nd2 = 0.f, nd3 = 0.f;
    if (ok0) { y0 = __ldg(&g_y[s.x]); nd0 = __ldg(&g_dinv[d.x]); }
    if (ok1) { y1 = __ldg(&g_y[s.y]); nd1 = __ldg(&g_dinv[d.y]); }
    if (ok2) { y2 = __ldg(&g_y[s.z]); nd2 = __ldg(&g_dinv[d.z]); }
    if (ok3) { y3 = __ldg(&g_y[s.w]); nd3 = __ldg(&g_dinv[d.w]); }
    if (ok0) {
        asm volatile("red.global.add.v4.f32 [%0], {%1, %2, %3, %4};"
                     :: "l"((float*)&g_p[d.x]),
                        "f"(y0.x), "f"(y0.y), "f"(y0.z), "f"(y0.w) : "memory");
        atomicAdd(&g_wacc[s.x], nd0);
    }
    if (ok1) {
        asm volatile("red.global.add.v4.f32 [%0], {%1, %2, %3, %4};"
                     :: "l"((float*)&g_p[d.y]),
                        "f"(y1.x), "f"(y1.y), "f"(y1.z), "f"(y1.w) : "memory");
        atomicAdd(&g_wacc[s.y], nd1);
    }
    if (ok2) {
        asm volatile("red.global.add.v4.f32 [%0], {%1, %2, %3, %4};"
                     :: "l"((float*)&g_p[d.z]),
                        "f"(y2.x), "f"(y2.y), "f"(y2.z), "f"(y2.w) : "memory");
        atomicAdd(&g_wacc[s.z], nd2);
    }
    if (ok3) {
        asm volatile("red.global.add.v4.f32 [%0], {%1, %2, %3, %4};"
                     :: "l"((float*)&g_p[d.w]),
                        "f"(y3.x), "f"(y3.y), "f"(y3.z), "f"(y3.w) : "memory");
        atomicAdd(&g_wacc[s.w], nd3);
    }
}

// K4: node pass, unroll x4 with EXACT coverage (no guards):
//   grid = 1250 blocks, 256 thr -> G = 1250*4 = 5000 node slots,
//   outer stride 4G = 20000, exactly 5 iterations; indices
//   {i0 + k*5000 : k=0..19, i0 in [0,5000)} tile [0,100000) exactly.
//   pfull = dinv[i]*(p[i] + y[i]); a = relu(pfull@W1+b1)
//   w = dinv[i]*(dinv[i]+wacc[i]); S += w*a
#define KN_GRID   1250
#define KN_G      (KN_GRID * 4)       // 5000
#define KN_STRIDE (KN_G * 4)          // 20000
__global__ void k_node(const float* __restrict__ W1,
                       const float* __restrict__ b1) {
    int j = threadIdx.x & 63;
    int g = threadIdx.x >> 6;              // 0..3
    float w0 = __ldg(&W1[j]),       w1 = __ldg(&W1[64 + j]);
    float w2 = __ldg(&W1[128 + j]), w3 = __ldg(&W1[192 + j]);
    float bb = __ldg(&b1[j]);
    float acc = 0.f;
    int i0 = blockIdx.x * 4 + g;           // [0, 5000)
    #pragma unroll 1
    for (int i = i0; i < N_NODES; i += KN_STRIDE) {
        int ia = i, ib = i + KN_G, ic = i + 2 * KN_G, id = i + 3 * KN_G;
        // batch all 16 loads first (MLP=16)
        float  da = g_dinv[ia], db = g_dinv[ib], dc = g_dinv[ic], dd = g_dinv[id];
        float4 pa = g_p[ia],    pb = g_p[ib],    pc = g_p[ic],    pd = g_p[id];
        float4 ya = g_y[ia],    yb = g_y[ib],    yc = g_y[ic],    yd = g_y[id];
        float  wa = g_wacc[ia], wb = g_wacc[ib], wc = g_wacc[ic], wd = g_wacc[id];
        float a0 = fmaf(da*(pa.x+ya.x), w0, fmaf(da*(pa.y+ya.y), w1,
                   fmaf(da*(pa.z+ya.z), w2, fmaf(da*(pa.w+ya.w), w3, bb))));
        float a1 = fmaf(db*(pb.x+yb.x), w0, fmaf(db*(pb.y+yb.y), w1,
                   fmaf(db*(pb.z+yb.z), w2, fmaf(db*(pb.w+yb.w), w3, bb))));
        float a2 = fmaf(dc*(pc.x+yc.x), w0, fmaf(dc*(pc.y+yc.y), w1,
                   fmaf(dc*(pc.z+yc.z), w2, fmaf(dc*(pc.w+yc.w), w3, bb))));
        float a3 = fmaf(dd*(pd.x+yd.x), w0, fmaf(dd*(pd.y+yd.y), w1,
                   fmaf(dd*(pd.z+yd.z), w2, fmaf(dd*(pd.w+yd.w), w3, bb))));
        acc = fmaf(da * (da + wa), fmaxf(a0, 0.f), acc);
        acc = fmaf(db * (db + wb), fmaxf(a1, 0.f), acc);
        acc = fmaf(dc * (dc + wc), fmaxf(a2, 0.f), acc);
        acc = fmaf(dd * (dd + wd), fmaxf(a3, 0.f), acc);
    }
    __shared__ float sh[256];
    sh[threadIdx.x] = acc;
    __syncthreads();
    if (threadIdx.x < 64) {
        float s = sh[threadIdx.x] + sh[threadIdx.x + 64]
                + sh[threadIdx.x + 128] + sh[threadIdx.x + 192];
        atomicAdd(&g_S[threadIdx.x], s);
    }
}

// K5: out[k] = (S @ W2)[k] / n + b2[k].  (S re-zeroed by next call's k_deg)
__global__ void k_final(const float* __restrict__ W2,
                        const float* __restrict__ b2,
                        float* __restrict__ out) {
    __shared__ float sS[64];
    int t = threadIdx.x;               // 0..63
    sS[t] = g_S[t];
    __syncthreads();
    if (t < 32) {
        float s = 0.f;
        #pragma unroll
        for (int j = 0; j < 64; j++) s = fmaf(sS[j], W2[j * 32 + t], s);
        out[t] = s * (1.0f / (float)N_NODES) + b2[t];
    }
}

extern "C" void kernel_launch(void* const* d_in, const int* in_sizes, int n_in,
                              void* d_out, int out_size) {
    const float4* x  = (const float4*)d_in[0];   // [100000, 4] f32
    const int*    ei = (const int*)d_in[1];      // [2, E] int32
    const float*  W1 = (const float*)d_in[2];    // [4, 64]
    const float*  b1 = (const float*)d_in[3];    // [64]
    const float*  W2 = (const float*)d_in[4];    // [64, 32]
    const float*  b2 = (const float*)d_in[5];    // [32]
    float*        out = (float*)d_out;           // [32]

    int E  = in_sizes[1] / 2;
    int E4 = E / 4;                              // E = 3.2M, divisible by 4
    const int4* src4 = (const int4*)ei;
    const int4* dst4 = (const int4*)(ei + E);

    const int T = 256;
    int nb_nodes  = (N_NODES + T - 1) / T;
    int nb_edges4 = (E4 + T - 1) / T;

    k_deg  <<<nb_edges4, T>>>(dst4, E4);
    k_prep <<<nb_nodes, T>>>(x);
    k_edge <<<nb_edges4, T>>>(src4, dst4, E4);
    k_node <<<KN_GRID, T>>>(W1, b1);
    k_final<<<1, 64>>>(W2, b2, out);
}

// round 7
// speedup vs baseline: 1.1128x; 1.1128x over previous
#include <cuda_runtime.h>
#include <cuda_bf16.h>

#define N_NODES 100000

// Scratch (zero-init at load). Replay invariant: deg=0 at entry (k_prep
// cleaned it); p/dw are fully overwritten by k_prep each call; S zeroed by k_deg.
__device__ float  g_deg [N_NODES];
__device__ float2 g_dw  [N_NODES];   // .x = dinv, .y = wacc (seeded with dinv)
__device__ float4 g_y   [N_NODES];   // x * dinv (pre-scaled source features)
__device__ float4 g_p   [N_NODES];   // seeded with y; += y[src] per dst edge
__device__ float  g_S   [64];        // sum_i w_i * relu(pfull_i @ W1 + b1)

// K1: in-degree count (dst half only), 4 edges/thread. Zeroes S.
__global__ void k_deg(const int4* __restrict__ dst4, int E4) {
    int t = blockIdx.x * blockDim.x + threadIdx.x;
    if (t < 64) g_S[t] = 0.0f;
    if (t >= E4) return;
    int4 d = dst4[t];
    if ((unsigned)d.x < (unsigned)N_NODES) atomicAdd(&g_deg[d.x], 1.0f);
    if ((unsigned)d.y < (unsigned)N_NODES) atomicAdd(&g_deg[d.y], 1.0f);
    if ((unsigned)d.z < (unsigned)N_NODES) atomicAdd(&g_deg[d.z], 1.0f);
    if ((unsigned)d.w < (unsigned)N_NODES) atomicAdd(&g_deg[d.w], 1.0f);
}

// K2: dinv = rsqrt(deg+1); y = x*dinv; seed p = y (self loop) and
// dw = {dinv, dinv} (wacc self loop). Resets deg for next replay.
__global__ void k_prep(const float4* __restrict__ x) {
    int i = blockIdx.x * blockDim.x + threadIdx.x;
    if (i >= N_NODES) return;
    float di = rsqrtf(g_deg[i] + 1.0f);
    g_deg[i] = 0.0f;                  // self-clean (line already owned)
    g_dw[i]  = make_float2(di, di);   // wacc seeded with self-loop dinv
    float4 xv = x[i];
    float4 yv = make_float4(xv.x * di, xv.y * di, xv.z * di, xv.w * di);
    g_y[i] = yv;
    g_p[i] = yv;                      // p seeded with self-loop message
}

// K3: fused edge pass, 4 edges/thread. Per edge (4 random L2 ops):
//   p[dst]  += y[src]          (RED.v4, payload straight from the gather)
//   dw[src].y += dinv[dst]     (RED scalar)
__global__ void k_edge(const int4* __restrict__ src4,
                       const int4* __restrict__ dst4,
                       int E4) {
    int t = blockIdx.x * blockDim.x + threadIdx.x;
    if (t >= E4) return;
    int4 s = src4[t];
    int4 d = dst4[t];
    bool ok0 = (unsigned)s.x < (unsigned)N_NODES && (unsigned)d.x < (unsigned)N_NODES;
    bool ok1 = (unsigned)s.y < (unsigned)N_NODES && (unsigned)d.y < (unsigned)N_NODES;
    bool ok2 = (unsigned)s.z < (unsigned)N_NODES && (unsigned)d.z < (unsigned)N_NODES;
    bool ok3 = (unsigned)s.w < (unsigned)N_NODES && (unsigned)d.w < (unsigned)N_NODES;
    float4 y0, y1, y2, y3;
    float nd0 = 0.f, nd1 = 0.f, nd2 = 0.f, nd3 = 0.f;
    if (ok0) { y0 = __ldg(&g_y[s.x]); nd0 = __ldg(&g_dw[d.x].x); }
    if (ok1) { y1 = __ldg(&g_y[s.y]); nd1 = __ldg(&g_dw[d.y].x); }
    if (ok2) { y2 = __ldg(&g_y[s.z]); nd2 = __ldg(&g_dw[d.z].x); }
    if (ok3) { y3 = __ldg(&g_y[s.w]); nd3 = __ldg(&g_dw[d.w].x); }
    if (ok0) {
        asm volatile("red.global.add.v4.f32 [%0], {%1, %2, %3, %4};"
                     :: "l"((float*)&g_p[d.x]),
                        "f"(y0.x), "f"(y0.y), "f"(y0.z), "f"(y0.w) : "memory");
        atomicAdd(&g_dw[s.x].y, nd0);
    }
    if (ok1) {
        asm volatile("red.global.add.v4.f32 [%0], {%1, %2, %3, %4};"
                     :: "l"((float*)&g_p[d.y]),
                        "f"(y1.x), "f"(y1.y), "f"(y1.z), "f"(y1.w) : "memory");
        atomicAdd(&g_dw[s.y].y, nd1);
    }
    if (ok2) {
        asm volatile("red.global.add.v4.f32 [%0], {%1, %2, %3, %4};"
                     :: "l"((float*)&g_p[d.z]),
                        "f"(y2.x), "f"(y2.y), "f"(y2.z), "f"(y2.w) : "memory");
        atomicAdd(&g_dw[s.z].y, nd2);
    }
    if (ok3) {
        asm volatile("red.global.add.v4.f32 [%0], {%1, %2, %3, %4};"
                     :: "l"((float*)&g_p[d.w]),
                        "f"(y3.x), "f"(y3.y), "f"(y3.z), "f"(y3.w) : "memory");
        atomicAdd(&g_dw[s.w].y, nd3);
    }
}

// K4: node pass, transposed layout: thread = node (coalesced loads), j-loop
// over 64 columns with W1 in smem; 64 per-thread accumulators reduced by a
// warp reduce-scatter butterfly (offs 16,8,4,2,1), then smem + global RED.
//   q = dinv * p (p already includes self loop)
//   a_j = relu(q . W1col_j + b_j);  S_j += (dinv*wacc) * a_j
#define KN_BLOCKS 200
#define KN_THREADS 256
#define KN_SPAN (KN_BLOCKS * KN_THREADS)   // 51200
__global__ void __launch_bounds__(KN_THREADS, 2)
k_node(const float* __restrict__ W1, const float* __restrict__ b1) {
    __shared__ float4 sW[64];
    __shared__ float  sB[64];
    __shared__ float  sS[64];
    int tid = threadIdx.x;
    if (tid < 64) {
        sW[tid] = make_float4(W1[tid], W1[64 + tid], W1[128 + tid], W1[192 + tid]);
        sB[tid] = b1[tid];
        sS[tid] = 0.0f;
    }
    __syncthreads();

    int t  = blockIdx.x * KN_THREADS + tid;      // [0, 51200)
    int i1 = t + KN_SPAN;
    bool has1 = (i1 < N_NODES);

    // coalesced node loads (2 per node)
    float4 p0 = g_p[t];
    float2 d0 = g_dw[t];
    float4 p1 = make_float4(0.f, 0.f, 0.f, 0.f);
    float2 d1 = make_float2(0.f, 0.f);
    if (has1) { p1 = g_p[i1]; d1 = g_dw[i1]; }

    float q0x = d0.x * p0.x, q0y = d0.x * p0.y, q0z = d0.x * p0.z, q0w = d0.x * p0.w;
    float q1x = d1.x * p1.x, q1y = d1.x * p1.y, q1z = d1.x * p1.z, q1w = d1.x * p1.w;
    float wn0 = d0.x * d0.y;
    float wn1 = d1.x * d1.y;      // 0 if !has1 -> contributes nothing

    float acc[64];
    #pragma unroll
    for (int j = 0; j < 64; j++) {
        float4 w = sW[j];
        float  b = sB[j];
        float z0 = fmaf(q0x, w.x, fmaf(q0y, w.y, fmaf(q0z, w.z, fmaf(q0w, w.w, b))));
        float z1 = fmaf(q1x, w.x, fmaf(q1y, w.y, fmaf(q1z, w.z, fmaf(q1w, w.w, b))));
        acc[j] = fmaf(wn0, fmaxf(z0, 0.f), wn1 * fmaxf(z1, 0.f));
    }

    // warp reduce-scatter butterfly: after round with off=o, live set halves;
    // lane bit o selects which half this lane keeps.
    int lane = tid & 31;
    #pragma unroll
    for (int k = 0; k < 32; k++) {
        float lo = acc[k], hi = acc[k + 32];
        bool up = (lane & 16);
        float keep = up ? hi : lo, give = up ? lo : hi;
        acc[k] = keep + __shfl_xor_sync(0xffffffffu, give, 16);
    }
    #pragma unroll
    for (int k = 0; k < 16; k++) {
        float lo = acc[k], hi = acc[k + 16];
        bool up = (lane & 8);
        float keep = up ? hi : lo, give = up ? lo : hi;
        acc[k] = keep + __shfl_xor_sync(0xffffffffu, give, 8);
    }
    #pragma unroll
    for (int k = 0; k < 8; k++) {
        float lo = acc[k], hi = acc[k + 8];
        bool up = (lane & 4);
        float keep = up ? hi : lo, give = up ? lo : hi;
        acc[k] = keep + __shfl_xor_sync(0xffffffffu, give, 4);
    }
    #pragma unroll
    for (int k = 0; k < 4; k++) {
        float lo = acc[k], hi = acc[k + 4];
        bool up = (lane & 2);
        float keep = up ? hi : lo, give = up ? lo : hi;
        acc[k] = keep + __shfl_xor_sync(0xffffffffu, give, 2);
    }
    #pragma unroll
    for (int k = 0; k < 2; k++) {
        float lo = acc[k], hi = acc[k + 2];
        bool up = (lane & 1);
        float keep = up ? hi : lo, give = up ? lo : hi;
        acc[k] = keep + __shfl_xor_sync(0xffffffffu, give, 1);
    }
    // lane holds warp-sums for j0 = bit-interleave(lane) and j0+1
    int j0 = 32 * ((lane >> 4) & 1) + 16 * ((lane >> 3) & 1)
           +  8 * ((lane >> 2) & 1) +  4 * ((lane >> 1) & 1)
           +  2 * (lane & 1);
    atomicAdd(&sS[j0],     acc[0]);
    atomicAdd(&sS[j0 + 1], acc[1]);
    __syncthreads();
    if (tid < 64) atomicAdd(&g_S[tid], sS[tid]);
}

// K5: out[k] = (S @ W2)[k] / n + b2[k].  (S re-zeroed by next call's k_deg)
__global__ void k_final(const float* __restrict__ W2,
                        const float* __restrict__ b2,
                        float* __restrict__ out) {
    __shared__ float sS[64];
    int t = threadIdx.x;               // 0..63
    sS[t] = g_S[t];
    __syncthreads();
    if (t < 32) {
        float s = 0.f;
        #pragma unroll
        for (int j = 0; j < 64; j++) s = fmaf(sS[j], W2[j * 32 + t], s);
        out[t] = s * (1.0f / (float)N_NODES) + b2[t];
    }
}

extern "C" void kernel_launch(void* const* d_in, const int* in_sizes, int n_in,
                              void* d_out, int out_size) {
    const float4* x  = (const float4*)d_in[0];   // [100000, 4] f32
    const int*    ei = (const int*)d_in[1];      // [2, E] int32
    const float*  W1 = (const float*)d_in[2];    // [4, 64]
    const float*  b1 = (const float*)d_in[3];    // [64]
    const float*  W2 = (const float*)d_in[4];    // [64, 32]
    const float*  b2 = (const float*)d_in[5];    // [32]
    float*        out = (float*)d_out;           // [32]

    int E  = in_sizes[1] / 2;
    int E4 = E / 4;                              // E = 3.2M, divisible by 4
    const int4* src4 = (const int4*)ei;
    const int4* dst4 = (const int4*)(ei + E);

    const int T = 256;
    int nb_nodes  = (N_NODES + T - 1) / T;
    int nb_edges4 = (E4 + T - 1) / T;

    k_deg  <<<nb_edges4, T>>>(dst4, E4);
    k_prep <<<nb_nodes, T>>>(x);
    k_edge <<<nb_edges4, T>>>(src4, dst4, E4);
    k_node <<<KN_BLOCKS, KN_THREADS>>>(W1, b1);
    k_final<<<1, 64>>>(W2, b2, out);
}

// round 8
// speedup vs baseline: 1.2046x; 1.0825x over previous
#include <cuda_runtime.h>
#include <cuda_bf16.h>

#define N_NODES 100000

// Scratch (zero-init at load). Replay invariant: deg=0 at entry (k_prep
// cleaned it); dinv/dw/p/y fully rewritten by k_prep each call; S zeroed by k_deg.
__device__ float  g_deg [N_NODES];
__device__ float  g_dinv[N_NODES];   // read-only during k_edge (gather stream)
__device__ float2 g_dw  [N_NODES];   // .x = dinv, .y = wacc; atomic-only during k_edge
__device__ float4 g_y   [N_NODES];   // x * dinv (pre-scaled source features)
__device__ float4 g_p   [N_NODES];   // seeded with y; += y[src] per dst edge
__device__ float  g_S   [64];        // sum_i w_i * relu(pfull_i @ W1 + b1)

// K1: in-degree count (dst half only), 4 edges/thread. Zeroes S.
__global__ void k_deg(const int4* __restrict__ dst4, int E4) {
    int t = blockIdx.x * blockDim.x + threadIdx.x;
    if (t < 64) g_S[t] = 0.0f;
    if (t >= E4) return;
    int4 d = dst4[t];
    if ((unsigned)d.x < (unsigned)N_NODES) atomicAdd(&g_deg[d.x], 1.0f);
    if ((unsigned)d.y < (unsigned)N_NODES) atomicAdd(&g_deg[d.y], 1.0f);
    if ((unsigned)d.z < (unsigned)N_NODES) atomicAdd(&g_deg[d.z], 1.0f);
    if ((unsigned)d.w < (unsigned)N_NODES) atomicAdd(&g_deg[d.w], 1.0f);
}

// K2: dinv = rsqrt(deg+1); y = x*dinv; seed p = y (self loop) and
// dw = {dinv, dinv} (wacc self loop). Resets deg for next replay.
__global__ void k_prep(const float4* __restrict__ x) {
    int i = blockIdx.x * blockDim.x + threadIdx.x;
    if (i >= N_NODES) return;
    float di = rsqrtf(g_deg[i] + 1.0f);
    g_deg[i]  = 0.0f;                 // self-clean (line already owned)
    g_dinv[i] = di;                   // clean gather copy for k_edge
    g_dw[i]   = make_float2(di, di);  // wacc seeded with self-loop dinv
    float4 xv = x[i];
    float4 yv = make_float4(xv.x * di, xv.y * di, xv.z * di, xv.w * di);
    g_y[i] = yv;
    g_p[i] = yv;                      // p seeded with self-loop message
}

// K3: fused edge pass, 4 edges/thread. Per edge (4 random L2 ops):
//   p[dst]   += y[src]         (RED.v4, payload straight from the gather)
//   dw[src].y += dinv[dst]     (RED scalar; gather hits g_dinv, RED hits g_dw
//                               -> read and atomic streams never share lines)
__global__ void k_edge(const int4* __restrict__ src4,
                       const int4* __restrict__ dst4,
                       int E4) {
    int t = blockIdx.x * blockDim.x + threadIdx.x;
    if (t >= E4) return;
    int4 s = src4[t];
    int4 d = dst4[t];
    bool ok0 = (unsigned)s.x < (unsigned)N_NODES && (unsigned)d.x < (unsigned)N_NODES;
    bool ok1 = (unsigned)s.y < (unsigned)N_NODES && (unsigned)d.y < (unsigned)N_NODES;
    bool ok2 = (unsigned)s.z < (unsigned)N_NODES && (unsigned)d.z < (unsigned)N_NODES;
    bool ok3 = (unsigned)s.w < (unsigned)N_NODES && (unsigned)d.w < (unsigned)N_NODES;
    float4 y0, y1, y2, y3;
    float nd0 = 0.f, nd1 = 0.f, nd2 = 0.f, nd3 = 0.f;
    if (ok0) { y0 = __ldg(&g_y[s.x]); nd0 = __ldg(&g_dinv[d.x]); }
    if (ok1) { y1 = __ldg(&g_y[s.y]); nd1 = __ldg(&g_dinv[d.y]); }
    if (ok2) { y2 = __ldg(&g_y[s.z]); nd2 = __ldg(&g_dinv[d.z]); }
    if (ok3) { y3 = __ldg(&g_y[s.w]); nd3 = __ldg(&g_dinv[d.w]); }
    if (ok0) {
        asm volatile("red.global.add.v4.f32 [%0], {%1, %2, %3, %4};"
                     :: "l"((float*)&g_p[d.x]),
                        "f"(y0.x), "f"(y0.y), "f"(y0.z), "f"(y0.w) : "memory");
        atomicAdd(&g_dw[s.x].y, nd0);
    }
    if (ok1) {
        asm volatile("red.global.add.v4.f32 [%0], {%1, %2, %3, %4};"
                     :: "l"((float*)&g_p[d.y]),
                        "f"(y1.x), "f"(y1.y), "f"(y1.z), "f"(y1.w) : "memory");
        atomicAdd(&g_dw[s.y].y, nd1);
    }
    if (ok2) {
        asm volatile("red.global.add.v4.f32 [%0], {%1, %2, %3, %4};"
                     :: "l"((float*)&g_p[d.z]),
                        "f"(y2.x), "f"(y2.y), "f"(y2.z), "f"(y2.w) : "memory");
        atomicAdd(&g_dw[s.z].y, nd2);
    }
    if (ok3) {
        asm volatile("red.global.add.v4.f32 [%0], {%1, %2, %3, %4};"
                     :: "l"((float*)&g_p[d.w]),
                        "f"(y3.x), "f"(y3.y), "f"(y3.z), "f"(y3.w) : "memory");
        atomicAdd(&g_dw[s.w].y, nd3);
    }
}

// K4: node pass, transposed: thread = node (coalesced), 64-col j-loop with W1
// in smem; 64 accumulators reduced by warp reduce-scatter butterfly.
//   q = dinv * p (p includes self loop); a_j = relu(q.W1col_j + b_j)
//   S_j += (dinv*wacc) * a_j
#define KN_BLOCKS 200
#define KN_THREADS 256
#define KN_SPAN (KN_BLOCKS * KN_THREADS)   // 51200
__global__ void __launch_bounds__(KN_THREADS, 2)
k_node(const float* __restrict__ W1, const float* __restrict__ b1) {
    __shared__ float4 sW[64];
    __shared__ float  sB[64];
    __shared__ float  sS[64];
    int tid = threadIdx.x;
    if (tid < 64) {
        sW[tid] = make_float4(W1[tid], W1[64 + tid], W1[128 + tid], W1[192 + tid]);
        sB[tid] = b1[tid];
        sS[tid] = 0.0f;
    }
    __syncthreads();

    int t  = blockIdx.x * KN_THREADS + tid;      // [0, 51200)
    int i1 = t + KN_SPAN;
    bool has1 = (i1 < N_NODES);

    float4 p0 = g_p[t];
    float2 d0 = g_dw[t];
    float4 p1 = make_float4(0.f, 0.f, 0.f, 0.f);
    float2 d1 = make_float2(0.f, 0.f);
    if (has1) { p1 = g_p[i1]; d1 = g_dw[i1]; }

    float q0x = d0.x * p0.x, q0y = d0.x * p0.y, q0z = d0.x * p0.z, q0w = d0.x * p0.w;
    float q1x = d1.x * p1.x, q1y = d1.x * p1.y, q1z = d1.x * p1.z, q1w = d1.x * p1.w;
    float wn0 = d0.x * d0.y;
    float wn1 = d1.x * d1.y;      // 0 if !has1

    float acc[64];
    #pragma unroll
    for (int j = 0; j < 64; j++) {
        float4 w = sW[j];
        float  b = sB[j];
        float z0 = fmaf(q0x, w.x, fmaf(q0y, w.y, fmaf(q0z, w.z, fmaf(q0w, w.w, b))));
        float z1 = fmaf(q1x, w.x, fmaf(q1y, w.y, fmaf(q1z, w.z, fmaf(q1w, w.w, b))));
        acc[j] = fmaf(wn0, fmaxf(z0, 0.f), wn1 * fmaxf(z1, 0.f));
    }

    int lane = tid & 31;
    #pragma unroll
    for (int k = 0; k < 32; k++) {
        float lo = acc[k], hi = acc[k + 32];
        bool up = (lane & 16);
        float keep = up ? hi : lo, give = up ? lo : hi;
        acc[k] = keep + __shfl_xor_sync(0xffffffffu, give, 16);
    }
    #pragma unroll
    for (int k = 0; k < 16; k++) {
        float lo = acc[k], hi = acc[k + 16];
        bool up = (lane & 8);
        float keep = up ? hi : lo, give = up ? lo : hi;
        acc[k] = keep + __shfl_xor_sync(0xffffffffu, give, 8);
    }
    #pragma unroll
    for (int k = 0; k < 8; k++) {
        float lo = acc[k], hi = acc[k + 8];
        bool up = (lane & 4);
        float keep = up ? hi : lo, give = up ? lo : hi;
        acc[k] = keep + __shfl_xor_sync(0xffffffffu, give, 4);
    }
    #pragma unroll
    for (int k = 0; k < 4; k++) {
        float lo = acc[k], hi = acc[k + 4];
        bool up = (lane & 2);
        float keep = up ? hi : lo, give = up ? lo : hi;
        acc[k] = keep + __shfl_xor_sync(0xffffffffu, give, 2);
    }
    #pragma unroll
    for (int k = 0; k < 2; k++) {
        float lo = acc[k], hi = acc[k + 2];
        bool up = (lane & 1);
        float keep = up ? hi : lo, give = up ? lo : hi;
        acc[k] = keep + __shfl_xor_sync(0xffffffffu, give, 1);
    }
    int j0 = 32 * ((lane >> 4) & 1) + 16 * ((lane >> 3) & 1)
           +  8 * ((lane >> 2) & 1) +  4 * ((lane >> 1) & 1)
           +  2 * (lane & 1);
    atomicAdd(&sS[j0],     acc[0]);
    atomicAdd(&sS[j0 + 1], acc[1]);
    __syncthreads();
    if (tid < 64) atomicAdd(&g_S[tid], sS[tid]);
}

// K5: out[k] = (S @ W2)[k] / n + b2[k].  (S re-zeroed by next call's k_deg)
__global__ void k_final(const float* __restrict__ W2,
                        const float* __restrict__ b2,
                        float* __restrict__ out) {
    __shared__ float sS[64];
    int t = threadIdx.x;               // 0..63
    sS[t] = g_S[t];
    __syncthreads();
    if (t < 32) {
        float s = 0.f;
        #pragma unroll
        for (int j = 0; j < 64; j++) s = fmaf(sS[j], W2[j * 32 + t], s);
        out[t] = s * (1.0f / (float)N_NODES) + b2[t];
    }
}

extern "C" void kernel_launch(void* const* d_in, const int* in_sizes, int n_in,
                              void* d_out, int out_size) {
    const float4* x  = (const float4*)d_in[0];   // [100000, 4] f32
    const int*    ei = (const int*)d_in[1];      // [2, E] int32
    const float*  W1 = (const float*)d_in[2];    // [4, 64]
    const float*  b1 = (const float*)d_in[3];    // [64]
    const float*  W2 = (const float*)d_in[4];    // [64, 32]
    const float*  b2 = (const float*)d_in[5];    // [32]
    float*        out = (float*)d_out;           // [32]

    int E  = in_sizes[1] / 2;
    int E4 = E / 4;                              // E = 3.2M, divisible by 4
    const int4* src4 = (const int4*)ei;
    const int4* dst4 = (const int4*)(ei + E);

    const int T = 256;
    int nb_nodes  = (N_NODES + T - 1) / T;
    int nb_edges4 = (E4 + T - 1) / T;

    k_deg  <<<nb_edges4, T>>>(dst4, E4);
    k_prep <<<nb_nodes, T>>>(x);
    k_edge <<<nb_edges4, T>>>(src4, dst4, E4);
    k_node <<<KN_BLOCKS, KN_THREADS>>>(W1, b1);
    k_final<<<1, 64>>>(W2, b2, out);
}